// round 2
// baseline (speedup 1.0000x reference)
#include <cuda_runtime.h>

#define C_CH   256
#define NBINS  49
#define SPOS   14
#define STAGE_PAD 257   // 49*257 floats of dynamic smem

// NHWC scratch for all 4 pyramid levels: 256 ch * (256^2+128^2+64^2+32^2) pixels
__device__ float g_nhwc[22282240];

__constant__ int   c_W[4]     = {256, 128, 64, 32};
__constant__ float c_scale[4] = {0.25f, 0.125f, 0.0625f, 0.03125f};
__constant__ int   c_base[4]  = {0, 65536, 81920, 86016};  // pixel offsets

// ---------------------------------------------------------------------------
// NCHW -> NHWC transpose (per level). in: [256, HW], writes g_nhwc[pix_base..]
// ---------------------------------------------------------------------------
__global__ void transpose_kernel(const float* __restrict__ in, int HW, int pix_base) {
    __shared__ float tile[32][33];
    int hw0 = blockIdx.x * 32;
    int c0  = blockIdx.y * 32;
    int tx = threadIdx.x, ty = threadIdx.y;
#pragma unroll
    for (int k = 0; k < 4; ++k) {
        tile[ty + k * 8][tx] = in[(size_t)(c0 + ty + k * 8) * HW + hw0 + tx];
    }
    __syncthreads();
#pragma unroll
    for (int k = 0; k < 4; ++k) {
        g_nhwc[(size_t)(pix_base + hw0 + ty + k * 8) * C_CH + c0 + tx] =
            tile[tx][ty + k * 8];
    }
}

// ---------------------------------------------------------------------------
// Main kernel: one block per roi. 256 threads = 4 bin-groups x 64 channel-quads.
// ---------------------------------------------------------------------------
__global__ __launch_bounds__(256)
void roi_max_kernel(const float* __restrict__ rois, float* __restrict__ out) {
    extern __shared__ float sh[];                 // [49][257] staging
    __shared__ int   s_lo[2][4][SPOS];            // [dim(x=0,y=1)][lvl][pos]
    __shared__ int   s_hi[2][4][SPOS];
    __shared__ float s_wl[2][4][SPOS];
    __shared__ float s_wh[2][4][SPOS];

    const int n = blockIdx.x;
    const int t = threadIdx.x;

    // --- precompute bilinear taps: 4 lvl x 2 dims x 14 positions = 112 tasks
    if (t < 112) {
        int lvl = t / 28;
        int rem = t % 28;
        int dim = rem / 14;            // 0 = x, 1 = y
        int s   = rem % 14;
        float scale = c_scale[lvl];
        float size  = (float)c_W[lvl];
        float start = rois[n * 5 + 1 + dim] * scale;
        float end   = rois[n * 5 + 3 + dim] * scale;
        float len   = fmaxf(end - start, 1.0f);
        float gpos  = (float)(s >> 1) + ((s & 1) ? 0.75f : 0.25f);
        float coord = start + gpos * (len * (1.0f / 7.0f));
        bool valid  = (coord > -1.0f) && (coord < size);
        float cc = fminf(fmaxf(coord, 0.0f), size - 1.0f);
        int lo = (int)cc;
        int hi = min(lo + 1, c_W[lvl] - 1);
        float wh = cc - (float)lo;
        float wl = 1.0f - wh;
        if (!valid) { wl = 0.0f; wh = 0.0f; }
        s_lo[dim][lvl][s] = lo;
        s_hi[dim][lvl][s] = hi;
        s_wl[dim][lvl][s] = wl;
        s_wh[dim][lvl][s] = wh;
    }
    __syncthreads();

    const int g = t >> 6;   // bin group 0..3
    const int q = t & 63;   // float4 channel index (channels 4q..4q+3)

    const float4* __restrict__ F = (const float4*)g_nhwc;

    for (int p = g; p < NBINS; p += 4) {
        int by = p / 7, bx = p - by * 7;
        float bx0, bx1, bx2, bx3;       // running max across levels
#pragma unroll
        for (int l = 0; l < 4; ++l) {
            const int W = c_W[l];
            const float4* __restrict__ FL = F + (size_t)c_base[l] * 64;
            float ax = 0.f, ay = 0.f, az = 0.f, aw = 0.f;
#pragma unroll
            for (int sy = 0; sy < 2; ++sy) {
                int iy  = 2 * by + sy;
                int ylo = s_lo[1][l][iy], yhi = s_hi[1][l][iy];
                float wyl = s_wl[1][l][iy], wyh = s_wh[1][l][iy];
#pragma unroll
                for (int sx = 0; sx < 2; ++sx) {
                    int ix  = 2 * bx + sx;
                    int xlo = s_lo[0][l][ix], xhi = s_hi[0][l][ix];
                    float wxl = s_wl[0][l][ix], wxh = s_wh[0][l][ix];
                    float w00 = wyl * wxl, w01 = wyl * wxh;
                    float w10 = wyh * wxl, w11 = wyh * wxh;
                    float4 v00 = FL[(ylo * W + xlo) * 64 + q];
                    float4 v01 = FL[(ylo * W + xhi) * 64 + q];
                    float4 v10 = FL[(yhi * W + xlo) * 64 + q];
                    float4 v11 = FL[(yhi * W + xhi) * 64 + q];
                    ax += w00 * v00.x + w01 * v01.x + w10 * v10.x + w11 * v11.x;
                    ay += w00 * v00.y + w01 * v01.y + w10 * v10.y + w11 * v11.y;
                    az += w00 * v00.z + w01 * v01.z + w10 * v10.z + w11 * v11.z;
                    aw += w00 * v00.w + w01 * v01.w + w10 * v10.w + w11 * v11.w;
                }
            }
            ax *= 0.25f; ay *= 0.25f; az *= 0.25f; aw *= 0.25f;
            if (l == 0) { bx0 = ax; bx1 = ay; bx2 = az; bx3 = aw; }
            else {
                bx0 = fmaxf(bx0, ax); bx1 = fmaxf(bx1, ay);
                bx2 = fmaxf(bx2, az); bx3 = fmaxf(bx3, aw);
            }
        }
        int cb = p * STAGE_PAD + 4 * q;
        sh[cb + 0] = bx0; sh[cb + 1] = bx1; sh[cb + 2] = bx2; sh[cb + 3] = bx3;
    }
    __syncthreads();

    // coalesced drain: out[n][c][p] flat = c*49 + p
    float* __restrict__ O = out + (size_t)n * (C_CH * NBINS);
#pragma unroll 7
    for (int idx = t; idx < C_CH * NBINS; idx += 256) {
        int c  = idx / 49;
        int p  = idx - c * 49;
        O[idx] = sh[p * STAGE_PAD + c];
    }
}

// ---------------------------------------------------------------------------
extern "C" void kernel_launch(void* const* d_in, const int* in_sizes, int n_in,
                              void* d_out, int out_size) {
    const float* f0   = (const float*)d_in[0];
    const float* f1   = (const float*)d_in[1];
    const float* f2   = (const float*)d_in[2];
    const float* f3   = (const float*)d_in[3];
    const float* rois = (const float*)d_in[4];
    int nrois = in_sizes[4] / 5;

    dim3 tb(32, 8);
    transpose_kernel<<<dim3(65536 / 32, 8), tb>>>(f0, 65536, 0);
    transpose_kernel<<<dim3(16384 / 32, 8), tb>>>(f1, 16384, 65536);
    transpose_kernel<<<dim3( 4096 / 32, 8), tb>>>(f2,  4096, 81920);
    transpose_kernel<<<dim3( 1024 / 32, 8), tb>>>(f3,  1024, 86016);

    size_t smem = (size_t)NBINS * STAGE_PAD * sizeof(float);  // 50372 B
    cudaFuncSetAttribute(roi_max_kernel,
                         cudaFuncAttributeMaxDynamicSharedMemorySize, (int)smem);
    roi_max_kernel<<<nrois, 256, smem>>>(rois, (float*)d_out);
}

// round 3
// speedup vs baseline: 1.4664x; 1.4664x over previous
#include <cuda_runtime.h>
#include <cuda_fp16.h>

#define C_CH   256
#define NBINS  49
#define SPOS   14
#define PAD    257

// NHWC fp16 scratch for all 4 pyramid levels: 256 ch * 87040 pixels = 44.5 MB
__device__ __half g_h[22282240];

__constant__ int   c_W[4]     = {256, 128, 64, 32};
__constant__ float c_scale[4] = {0.25f, 0.125f, 0.0625f, 0.03125f};
__constant__ int   c_base[4]  = {0, 65536, 81920, 86016};  // pixel offsets

// ---------------------------------------------------------------------------
// NCHW fp32 -> NHWC fp16 transpose (per level).
// ---------------------------------------------------------------------------
__global__ void transpose_kernel(const float* __restrict__ in, int HW, int pix_base) {
    __shared__ float tile[32][33];
    int hw0 = blockIdx.x * 32;
    int c0  = blockIdx.y * 32;
    int tx = threadIdx.x, ty = threadIdx.y;
#pragma unroll
    for (int k = 0; k < 4; ++k) {
        tile[ty + k * 8][tx] = in[(size_t)(c0 + ty + k * 8) * HW + hw0 + tx];
    }
    __syncthreads();
#pragma unroll
    for (int k = 0; k < 4; ++k) {
        g_h[(size_t)(pix_base + hw0 + ty + k * 8) * C_CH + c0 + tx] =
            __float2half_rn(tile[tx][ty + k * 8]);
    }
}

// ---------------------------------------------------------------------------
// Main kernel: one block per roi. 8 warps; warp = contiguous bin chunk,
// lane o = channel octet (channels 8o..8o+7). Level-outer loop for L1 reuse;
// cross-level max lives in swizzled smem staging.
// ---------------------------------------------------------------------------
__global__ __launch_bounds__(256)
void roi_max_kernel(const float* __restrict__ rois, float* __restrict__ out) {
    extern __shared__ float sh[];                 // [49][257] staging, swizzled
    __shared__ int   s_lo[2][4][SPOS];            // [dim(x=0,y=1)][lvl][pos]
    __shared__ int   s_hi[2][4][SPOS];
    __shared__ float s_wl[2][4][SPOS];
    __shared__ float s_wh[2][4][SPOS];

    const int n = blockIdx.x;
    const int t = threadIdx.x;

    // --- precompute bilinear taps: 4 lvl x 2 dims x 14 positions = 112 tasks
    if (t < 112) {
        int lvl = t / 28;
        int rem = t % 28;
        int dim = rem / 14;            // 0 = x, 1 = y
        int s   = rem % 14;
        float scale = c_scale[lvl];
        float size  = (float)c_W[lvl];
        float start = rois[n * 5 + 1 + dim] * scale;
        float end   = rois[n * 5 + 3 + dim] * scale;
        float len   = fmaxf(end - start, 1.0f);
        float gpos  = (float)(s >> 1) + ((s & 1) ? 0.75f : 0.25f);
        float coord = start + gpos * (len * (1.0f / 7.0f));
        bool valid  = (coord > -1.0f) && (coord < size);
        float cc = fminf(fmaxf(coord, 0.0f), size - 1.0f);
        int lo = (int)cc;
        int hi = min(lo + 1, c_W[lvl] - 1);
        float wh = cc - (float)lo;
        float wl = 1.0f - wh;
        if (!valid) { wl = 0.0f; wh = 0.0f; }
        s_lo[dim][lvl][s] = lo;
        s_hi[dim][lvl][s] = hi;
        s_wl[dim][lvl][s] = wl;
        s_wh[dim][lvl][s] = wh;
    }
    __syncthreads();

    const int g  = t >> 5;                 // warp id 0..7
    const int o  = t & 31;                 // channel octet
    const int p0 = (NBINS * g) >> 3;       // contiguous bin range per warp
    const int p1 = (NBINS * (g + 1)) >> 3;
    const int r  = o >> 2;                 // swizzle rotation (0..7)

    const uint4* __restrict__ F = (const uint4*)g_h;

#pragma unroll
    for (int l = 0; l < 4; ++l) {
        const int W = c_W[l];
        const uint4* __restrict__ FL = F + (size_t)c_base[l] * 32;
        for (int p = p0; p < p1; ++p) {
            int by = p / 7, bx = p - by * 7;
            float a[8];
#pragma unroll
            for (int j = 0; j < 8; ++j) a[j] = 0.0f;
#pragma unroll
            for (int sy = 0; sy < 2; ++sy) {
                int iy  = 2 * by + sy;
                int ylo = s_lo[1][l][iy], yhi = s_hi[1][l][iy];
                float wyl = s_wl[1][l][iy], wyh = s_wh[1][l][iy];
#pragma unroll
                for (int sx = 0; sx < 2; ++sx) {
                    int ix  = 2 * bx + sx;
                    int xlo = s_lo[0][l][ix], xhi = s_hi[0][l][ix];
                    float wxl = s_wl[0][l][ix], wxh = s_wh[0][l][ix];
                    float w00 = wyl * wxl, w01 = wyl * wxh;
                    float w10 = wyh * wxl, w11 = wyh * wxh;
                    uint4 v00 = FL[(ylo * W + xlo) * 32 + o];
                    uint4 v01 = FL[(ylo * W + xhi) * 32 + o];
                    uint4 v10 = FL[(yhi * W + xlo) * 32 + o];
                    uint4 v11 = FL[(yhi * W + xhi) * 32 + o];
                    const __half2* h00 = (const __half2*)&v00;
                    const __half2* h01 = (const __half2*)&v01;
                    const __half2* h10 = (const __half2*)&v10;
                    const __half2* h11 = (const __half2*)&v11;
#pragma unroll
                    for (int i = 0; i < 4; ++i) {
                        float2 f00 = __half22float2(h00[i]);
                        float2 f01 = __half22float2(h01[i]);
                        float2 f10 = __half22float2(h10[i]);
                        float2 f11 = __half22float2(h11[i]);
                        a[2*i]   += w00*f00.x + w01*f01.x + w10*f10.x + w11*f11.x;
                        a[2*i+1] += w00*f00.y + w01*f01.y + w10*f10.y + w11*f11.y;
                    }
                }
            }
            // swizzled staging update: slot 8o + ((j+r)&7) is bank-conflict-free
            float* base = &sh[p * PAD + 8 * o];
            if (l == 0) {
#pragma unroll
                for (int j = 0; j < 8; ++j) base[(j + r) & 7] = a[j] * 0.25f;
            } else {
#pragma unroll
                for (int j = 0; j < 8; ++j) {
                    int s = (j + r) & 7;
                    base[s] = fmaxf(base[s], a[j] * 0.25f);
                }
            }
        }
    }
    __syncthreads();

    // coalesced drain: out[n][c][p] flat = c*49 + p (un-swizzle channel)
    float* __restrict__ O = out + (size_t)n * (C_CH * NBINS);
#pragma unroll 7
    for (int idx = t; idx < C_CH * NBINS; idx += 256) {
        int c = idx / 49;
        int p = idx - c * 49;
        int oo = c >> 3;
        O[idx] = sh[p * PAD + 8 * oo + (((c & 7) + (oo >> 2)) & 7)];
    }
}

// ---------------------------------------------------------------------------
extern "C" void kernel_launch(void* const* d_in, const int* in_sizes, int n_in,
                              void* d_out, int out_size) {
    const float* f0   = (const float*)d_in[0];
    const float* f1   = (const float*)d_in[1];
    const float* f2   = (const float*)d_in[2];
    const float* f3   = (const float*)d_in[3];
    const float* rois = (const float*)d_in[4];
    int nrois = in_sizes[4] / 5;

    dim3 tb(32, 8);
    transpose_kernel<<<dim3(65536 / 32, 8), tb>>>(f0, 65536, 0);
    transpose_kernel<<<dim3(16384 / 32, 8), tb>>>(f1, 16384, 65536);
    transpose_kernel<<<dim3( 4096 / 32, 8), tb>>>(f2,  4096, 81920);
    transpose_kernel<<<dim3( 1024 / 32, 8), tb>>>(f3,  1024, 86016);

    size_t smem = (size_t)NBINS * PAD * sizeof(float);  // 50372 B
    cudaFuncSetAttribute(roi_max_kernel,
                         cudaFuncAttributeMaxDynamicSharedMemorySize, (int)smem);
    roi_max_kernel<<<nrois, 256, smem>>>(rois, (float*)d_out);
}